// round 7
// baseline (speedup 1.0000x reference)
#include <cuda_runtime.h>
#include <cuda_bf16.h>
#include <cstdint>

#define B_  16
#define T_  512
#define H_  2048
#define TH_ (T_ * H_)        // 1048576
#define WLD 4096             // W row stride (floats)
#define NBLK 128

// ---------------- device globals -------------------------------------------
// per-block progress flags: flag[gi*4 + ki] = last completed step t
__device__ unsigned g_flag[NBLK];

__device__ __nv_bfloat16 g_xh[(size_t)B_ * T_ * H_];
__device__ __nv_bfloat16 g_xl[(size_t)B_ * T_ * H_];
__device__ __nv_bfloat16 g_wxh[(size_t)H_ * H_];
__device__ __nv_bfloat16 g_wxl[(size_t)H_ * H_];
__device__ __nv_bfloat16 g_whh[(size_t)H_ * H_];
__device__ __nv_bfloat16 g_whl[(size_t)H_ * H_];

__global__ void zero_flag_kernel() { g_flag[threadIdx.x] = 0u; }
__global__ void dummy_kernel() {}

// ---------------- helpers ---------------------------------------------------
__device__ __forceinline__ uint32_t smem_u32(const void* p) {
    return (uint32_t)__cvta_generic_to_shared(p);
}
__device__ __forceinline__ void cp16(uint32_t s, const void* g) {
    asm volatile("cp.async.cg.shared.global [%0], [%1], 16;" :: "r"(s), "l"(g));
}
#define CP_COMMIT() asm volatile("cp.async.commit_group;")

__device__ __forceinline__ void ldsm4(uint32_t (&r)[4], uint32_t addr) {
    asm volatile("ldmatrix.sync.aligned.m8n8.x4.shared.b16 {%0,%1,%2,%3}, [%4];"
                 : "=r"(r[0]), "=r"(r[1]), "=r"(r[2]), "=r"(r[3]) : "r"(addr));
}
__device__ __forceinline__ void mma16816(float (&c)[4], const uint32_t (&a)[4],
                                         uint32_t b0, uint32_t b1) {
    asm volatile("mma.sync.aligned.m16n8k16.row.col.f32.bf16.bf16.f32 "
                 "{%0,%1,%2,%3}, {%4,%5,%6,%7}, {%8,%9}, {%0,%1,%2,%3};"
                 : "+f"(c[0]), "+f"(c[1]), "+f"(c[2]), "+f"(c[3])
                 : "r"(a[0]), "r"(a[1]), "r"(a[2]), "r"(a[3]), "r"(b0), "r"(b1));
}
__device__ __forceinline__ float4 ld_cg4(const float* p) {
    float4 v;
    asm volatile("ld.global.cg.v4.f32 {%0,%1,%2,%3}, [%4];"
                 : "=f"(v.x), "=f"(v.y), "=f"(v.z), "=f"(v.w) : "l"(p));
    return v;
}
__device__ __forceinline__ void red_add_v2(float* p, float a, float b) {
    asm volatile("red.global.add.v2.f32 [%0], {%1, %2};"
                 :: "l"(p), "f"(a), "f"(b) : "memory");
}

// ---------------- prepass: hi/lo bf16 splits --------------------------------
__global__ void split_x_kernel(const float* __restrict__ x) {
    size_t fi = (size_t)blockIdx.x * blockDim.x + threadIdx.x;
    if (fi >= (size_t)B_ * T_ * H_ / 4) return;
    float4 v = *(const float4*)(x + fi * 4);
    union { __nv_bfloat16 b[4]; uint2 u; } hh, ll;
    float f[4] = {v.x, v.y, v.z, v.w};
#pragma unroll
    for (int i = 0; i < 4; i++) {
        hh.b[i] = __float2bfloat16_rn(f[i]);
        ll.b[i] = __float2bfloat16_rn(f[i] - __bfloat162float(hh.b[i]));
    }
    *(uint2*)(g_xh + fi * 4) = hh.u;
    *(uint2*)(g_xl + fi * 4) = ll.u;
}

__global__ void split_w_kernel(const float* __restrict__ W) {
    size_t fi = (size_t)blockIdx.x * blockDim.x + threadIdx.x;
    if (fi >= (size_t)H_ * H_ / 4) return;
    int g = (int)(fi >> 9);
    int c = (int)(fi & 511) * 4;
    const float* base = W + (size_t)g * WLD;

    float4 v = *(const float4*)(base + c);
    union { __nv_bfloat16 b[4]; uint2 u; } hh, ll;
    float f[4] = {v.x, v.y, v.z, v.w};
#pragma unroll
    for (int i = 0; i < 4; i++) {
        hh.b[i] = __float2bfloat16_rn(f[i]);
        ll.b[i] = __float2bfloat16_rn(f[i] - __bfloat162float(hh.b[i]));
    }
    *(uint2*)(g_wxh + (size_t)g * H_ + c) = hh.u;
    *(uint2*)(g_wxl + (size_t)g * H_ + c) = ll.u;

    v = *(const float4*)(base + H_ + c);
    float f2[4] = {v.x, v.y, v.z, v.w};
#pragma unroll
    for (int i = 0; i < 4; i++) {
        hh.b[i] = __float2bfloat16_rn(f2[i]);
        ll.b[i] = __float2bfloat16_rn(f2[i] - __bfloat162float(hh.b[i]));
    }
    *(uint2*)(g_whh + (size_t)g * H_ + c) = hh.u;
    *(uint2*)(g_whl + (size_t)g * H_ + c) = ll.u;
}

// ===========================================================================
// Phase 1: u[m,g] = sum_k x[m,k] W[g,k] + b[g], 3x bf16 split mma.
// 128x128x32 tiles, 4-stage cp.async pipeline (R5 measured-best version).
// ===========================================================================
#define P1_ST 40
#define P1_TILE (128 * P1_ST)
#define P1_NS 4
#define P1_SMEM_BYTES (2 * P1_NS * P1_TILE * 2)   // 81920

__global__ __launch_bounds__(256, 2)
void gemm_u_mma(const float* __restrict__ bias, float* __restrict__ out)
{
    extern __shared__ __align__(16) __nv_bfloat16 sm[];
    __nv_bfloat16* As[P1_NS];
    __nv_bfloat16* Bs[P1_NS];
#pragma unroll
    for (int s = 0; s < P1_NS; s++) {
        As[s] = sm + s * P1_TILE;
        Bs[s] = sm + (P1_NS + s) * P1_TILE;
    }

    const int tid = threadIdx.x, lane = tid & 31, wid = tid >> 5;
    const int m0 = blockIdx.y * 128, g0 = blockIdx.x * 128;
    const int wm = wid & 3, wn = wid >> 2;

    const __nv_bfloat16* Ag[3] = { g_xh, g_xh, g_xl };
    const __nv_bfloat16* Bg[3] = { g_wxh, g_wxl, g_wxh };

    const int lrow = tid >> 1;
    const int lco  = (tid & 1) * 16;

    float acc[2][8][4];
#pragma unroll
    for (int i = 0; i < 2; i++)
#pragma unroll
        for (int j = 0; j < 8; j++)
#pragma unroll
            for (int q = 0; q < 4; q++) acc[i][j][q] = 0.0f;

#define P1_ISSUE(st, it) do {                                                  \
        int _p = (it) >> 6, _kk = ((it) & 63) * 32;                            \
        const __nv_bfloat16* _ga = Ag[_p] + (size_t)(m0 + lrow) * H_ + _kk + lco; \
        const __nv_bfloat16* _gb = Bg[_p] + (size_t)(g0 + lrow) * H_ + _kk + lco; \
        uint32_t _sa = smem_u32(As[st] + lrow * P1_ST + lco);                  \
        uint32_t _sb = smem_u32(Bs[st] + lrow * P1_ST + lco);                  \
        cp16(_sa, _ga); cp16(_sa + 16, _ga + 8);                               \
        cp16(_sb, _gb); cp16(_sb + 16, _gb + 8);                               \
    } while (0)

    P1_ISSUE(0, 0); CP_COMMIT();
    P1_ISSUE(1, 1); CP_COMMIT();
    P1_ISSUE(2, 2); CP_COMMIT();

    const int NT = 192;
    for (int it = 0; it < NT; ++it) {
        asm volatile("cp.async.wait_group 2;");
        __syncthreads();
        int nx = it + 3;
        if (nx < NT) { P1_ISSUE(nx & 3, nx); }
        CP_COMMIT();

        const __nv_bfloat16* A_s = As[it & 3];
        const __nv_bfloat16* B_s = Bs[it & 3];
#pragma unroll
        for (int kq = 0; kq < 2; kq++) {
            uint32_t a[2][4];
#pragma unroll
            for (int mt = 0; mt < 2; mt++)
                ldsm4(a[mt], smem_u32(A_s + (wm * 32 + mt * 16 + (lane & 15)) * P1_ST
                                          + kq * 16 + ((lane >> 4) << 3)));
            uint32_t bf[4][4];
#pragma unroll
            for (int ng = 0; ng < 4; ng++)
                ldsm4(bf[ng], smem_u32(B_s + (wn * 64 + ng * 16 + (lane & 7) + ((lane & 16) >> 1)) * P1_ST
                                           + kq * 16 + (lane & 8)));
#pragma unroll
            for (int mt = 0; mt < 2; mt++)
#pragma unroll
                for (int ng = 0; ng < 4; ng++) {
                    mma16816(acc[mt][2 * ng],     a[mt], bf[ng][0], bf[ng][1]);
                    mma16816(acc[mt][2 * ng + 1], a[mt], bf[ng][2], bf[ng][3]);
                }
        }
    }

    const int r0 = lane >> 2, c0 = (lane & 3) * 2;
#pragma unroll
    for (int mt = 0; mt < 2; mt++) {
        int m = m0 + wm * 32 + mt * 16 + r0;
#pragma unroll
        for (int nt = 0; nt < 8; nt++) {
            int g = g0 + wn * 64 + nt * 8 + c0;
            float bx = bias[g], by = bias[g + 1];
            float2 v0 = { acc[mt][nt][0] + bx, acc[mt][nt][1] + by };
            float2 v1 = { acc[mt][nt][2] + bx, acc[mt][nt][3] + by };
            *(float2*)(out + (size_t)m * H_ + g)       = v0;
            *(float2*)(out + (size_t)(m + 8) * H_ + g) = v1;
        }
    }
}

// ===========================================================================
// Phase 2: persistent scan with LOCAL dataflow sync (no global barrier).
// Grid 128 = 32 g-tiles (64) x 4 k-tiles (512).
// Block (gi,ki) consumes h[:, 512ki .. 512ki+512) = outputs of g-tiles
// [8ki, 8ki+8), i.e. the 32 blocks flag[32ki .. 32ki+32).
// flag[gi*4+ki] = t is stored with release after the block's step-t REDs.
// Writes for step t go to out[:, t, :] (disjoint per t) -> any skew is safe.
// ===========================================================================
#define GT 64
#define KT 512
#define WST 520
#define HST 520
#define O_WHH 0
#define O_WHL (GT * WST)
#define O_HH  (2 * GT * WST)
#define O_HL  (O_HH + B_ * HST)
#define SC_SMEM_ELEMS (O_HL + B_ * HST)
#define SC_SMEM_BYTES (SC_SMEM_ELEMS * 2)  // 166400

__global__ __launch_bounds__(256, 1)
void rnn_scan4(float* __restrict__ out)
{
    extern __shared__ __align__(16) __nv_bfloat16 sm[];
    __nv_bfloat16* whh_s = sm + O_WHH;
    __nv_bfloat16* whl_s = sm + O_WHL;
    __nv_bfloat16* hh_s  = sm + O_HH;
    __nv_bfloat16* hl_s  = sm + O_HL;

    const int tid = threadIdx.x, lane = tid & 31, wid = tid >> 5;
    const int gi = blockIdx.x & 31;
    const int ki = blockIdx.x >> 5;
    const int g0 = gi * GT;
    const int k0 = ki * KT;

    // ---- stage Wh hi/lo slice: 64 g-rows x 512 k ----
    for (int i = tid; i < GT * (KT / 8); i += 256) {
        int row = i >> 6;
        int c8  = (i & 63) * 8;
        *(uint4*)(whh_s + row * WST + c8) =
            *(const uint4*)(g_whh + (size_t)(g0 + row) * H_ + k0 + c8);
        *(uint4*)(whl_s + row * WST + c8) =
            *(const uint4*)(g_whl + (size_t)(g0 + row) * H_ + k0 + c8);
    }
    __syncthreads();

    const int n0w = wid * 8;
    const int r0 = lane >> 2, c0 = (lane & 3) * 2;

    const uint32_t aHb = smem_u32(hh_s + (lane & 15) * HST + ((lane >> 4) << 3));
    const uint32_t aLb = smem_u32(hl_s + (lane & 15) * HST + ((lane >> 4) << 3));
    const int brow = n0w + (lane & 7);
    const int bcol = ((lane >> 3) & 3) * 8;
    const uint32_t bHb = smem_u32(whh_s + brow * WST + bcol);
    const uint32_t bLb = smem_u32(whl_s + brow * WST + bcol);

    unsigned* myflag = &g_flag[gi * 4 + ki];
    unsigned* depflags = &g_flag[32 * ki];

    for (int t = 1; t < T_; ++t) {
        // ---- wait for the 32 producers of my k-slice to finish step t-1 ----
        if (t >= 2) {
            if (wid == 0) {
                const unsigned tgt = (unsigned)(t - 1);
                unsigned v;
                do {
                    asm volatile("ld.acquire.gpu.global.u32 %0, [%1];"
                                 : "=r"(v) : "l"(depflags + lane) : "memory");
                } while (__ballot_sync(0xFFFFFFFFu, v < tgt));
            }
            __syncthreads();
        }

        // ---- load h_{t-1} k-slice (16 x 512 fp32), split into smem ----
#pragma unroll
        for (int r = 0; r < 8; r++) {
            int fi = tid + r * 256;
            int b  = fi >> 7;
            int c4 = fi & 127;
            float4 h4 = ld_cg4(out + (size_t)b * TH_ + (size_t)(t - 1) * H_ + k0 + c4 * 4);
            union { __nv_bfloat16 bb[4]; uint2 u; } th, tl;
            float f[4] = {h4.x, h4.y, h4.z, h4.w};
#pragma unroll
            for (int q = 0; q < 4; q++) {
                th.bb[q] = __float2bfloat16_rn(f[q]);
                tl.bb[q] = __float2bfloat16_rn(f[q] - __bfloat162float(th.bb[q]));
            }
            *(uint2*)(hh_s + b * HST + c4 * 4) = th.u;
            *(uint2*)(hl_s + b * HST + c4 * 4) = tl.u;
        }
        __syncthreads();

        // ---- compute: 16 k32 chunks, 3 accumulators ----
        float acc0[4], acc1[4], acc2[4];
#pragma unroll
        for (int q = 0; q < 4; q++) { acc0[q] = 0.0f; acc1[q] = 0.0f; acc2[q] = 0.0f; }

#pragma unroll
        for (int kc = 0; kc < 16; kc++) {
            const uint32_t off = kc * 64;
            uint32_t ah0[4], ah1[4], al0[4], al1[4], bh[4], bl[4];
            ldsm4(bh,  bHb + off);
            ldsm4(ah0, aHb + off);
            ldsm4(ah1, aHb + off + 32);
            ldsm4(bl,  bLb + off);
            ldsm4(al0, aLb + off);
            ldsm4(al1, aLb + off + 32);
            mma16816(acc0, ah0, bh[0], bh[1]);
            mma16816(acc1, ah0, bl[0], bl[1]);
            mma16816(acc2, al0, bh[0], bh[1]);
            mma16816(acc0, ah1, bh[2], bh[3]);
            mma16816(acc1, ah1, bl[2], bl[3]);
            mma16816(acc2, al1, bh[2], bh[3]);
        }

        // ---- epilogue: 2 vector REDs into out[:, t, :] (holds u_t) ----
#pragma unroll
        for (int q = 0; q < 4; q++) acc0[q] += acc1[q] + acc2[q];
        red_add_v2(out + (size_t)r0 * TH_ + (size_t)t * H_ + g0 + n0w + c0,
                   acc0[0], acc0[1]);
        red_add_v2(out + (size_t)(r0 + 8) * TH_ + (size_t)t * H_ + g0 + n0w + c0,
                   acc0[2], acc0[3]);

        // ---- publish progress: flag = t (release) ----
        __syncthreads();          // all CTA REDs issued before the release
        if (tid == 0) {
            asm volatile("st.release.gpu.global.u32 [%0], %1;"
                         :: "l"(myflag), "r"((unsigned)t) : "memory");
        }
        // NOTE: hh_s/hl_s reuse next iter is protected by the sync above
        // (every thread passed it after finishing its ldsm reads).
    }
}

// ---------------- h_last copy ----------------------------------------------
__global__ void hlast_kernel(const float* __restrict__ out,
                             float* __restrict__ hlast)
{
    int i = blockIdx.x * blockDim.x + threadIdx.x;
    if (i < B_ * H_) {
        int b = i / H_;
        int g = i % H_;
        hlast[i] = out[(size_t)b * TH_ + (size_t)(T_ - 1) * H_ + g];
    }
}

// ---------------- launch ----------------------------------------------------
extern "C" void kernel_launch(void* const* d_in, const int* in_sizes, int n_in,
                              void* d_out, int out_size)
{
    const float* x  = (const float*)d_in[0];
    const float* W  = (const float*)d_in[1];
    const float* bi = (const float*)d_in[2];
    float* out = (float*)d_out;

    cudaFuncSetAttribute(gemm_u_mma,
                         cudaFuncAttributeMaxDynamicSharedMemorySize,
                         P1_SMEM_BYTES);
    cudaFuncSetAttribute(rnn_scan4,
                         cudaFuncAttributeMaxDynamicSharedMemorySize,
                         SC_SMEM_BYTES);

    zero_flag_kernel<<<1, NBLK>>>();
    split_x_kernel<<<(B_ * T_ * H_ / 4 + 255) / 256, 256>>>(x);
    split_w_kernel<<<(H_ * H_ / 4 + 255) / 256, 256>>>(W);

    dim3 ggrid(H_ / 128, (B_ * T_) / 128);   // (16, 64)
    gemm_u_mma<<<ggrid, 256, P1_SMEM_BYTES>>>(bi, out);

    dummy_kernel<<<1, 32>>>();   // pads launch count so ncu -s 5 hits the scan

    rnn_scan4<<<NBLK, 256, SC_SMEM_BYTES>>>(out);

    if (out_size >= B_ * T_ * H_ + B_ * H_) {
        hlast_kernel<<<(B_ * H_ + 255) / 256, 256>>>(out, out + (size_t)B_ * T_ * H_);
    }
}

// round 8
// speedup vs baseline: 1.2334x; 1.2334x over previous
#include <cuda_runtime.h>
#include <cuda_bf16.h>
#include <cstdint>

#define B_  16
#define T_  512
#define H_  2048
#define TH_ (T_ * H_)        // 1048576
#define WLD 4096             // W row stride (floats)
#define NBLK 128

// ---------------- device globals -------------------------------------------
__device__ unsigned g_bar[T_];

__device__ __nv_bfloat16 g_xh[(size_t)B_ * T_ * H_];
__device__ __nv_bfloat16 g_xl[(size_t)B_ * T_ * H_];
__device__ __nv_bfloat16 g_wxh[(size_t)H_ * H_];
__device__ __nv_bfloat16 g_wxl[(size_t)H_ * H_];
__device__ __nv_bfloat16 g_whh[(size_t)H_ * H_];
__device__ __nv_bfloat16 g_whl[(size_t)H_ * H_];

__global__ void zero_bar_kernel() { g_bar[threadIdx.x] = 0u; }

// ---------------- helpers ---------------------------------------------------
__device__ __forceinline__ uint32_t smem_u32(const void* p) {
    return (uint32_t)__cvta_generic_to_shared(p);
}
__device__ __forceinline__ void cp16(uint32_t s, const void* g) {
    asm volatile("cp.async.cg.shared.global [%0], [%1], 16;" :: "r"(s), "l"(g));
}
#define CP_COMMIT() asm volatile("cp.async.commit_group;")

__device__ __forceinline__ void ldsm4(uint32_t (&r)[4], uint32_t addr) {
    asm volatile("ldmatrix.sync.aligned.m8n8.x4.shared.b16 {%0,%1,%2,%3}, [%4];"
                 : "=r"(r[0]), "=r"(r[1]), "=r"(r[2]), "=r"(r[3]) : "r"(addr));
}
__device__ __forceinline__ void mma16816(float (&c)[4], const uint32_t (&a)[4],
                                         uint32_t b0, uint32_t b1) {
    asm volatile("mma.sync.aligned.m16n8k16.row.col.f32.bf16.bf16.f32 "
                 "{%0,%1,%2,%3}, {%4,%5,%6,%7}, {%8,%9}, {%0,%1,%2,%3};"
                 : "+f"(c[0]), "+f"(c[1]), "+f"(c[2]), "+f"(c[3])
                 : "r"(a[0]), "r"(a[1]), "r"(a[2]), "r"(a[3]), "r"(b0), "r"(b1));
}
__device__ __forceinline__ float4 ld_cg4(const float* p) {
    float4 v;
    asm volatile("ld.global.cg.v4.f32 {%0,%1,%2,%3}, [%4];"
                 : "=f"(v.x), "=f"(v.y), "=f"(v.z), "=f"(v.w) : "l"(p));
    return v;
}

// ---------------- prepass: hi/lo bf16 splits (merged into ONE kernel) -------
// blocks [0, XB): x  -> g_xh/g_xl      (XB = B*T*H/4/256)
// blocks [XB, XB+WB): W -> g_wx*/g_wh* (WB = H*H/4/256)
#define XB ((B_ * T_ * H_ / 4) / 256)      // 16384
#define WB ((H_ * H_ / 4) / 256)           // 4096

__global__ void split_xw_kernel(const float* __restrict__ x,
                                const float* __restrict__ W)
{
    int bb = blockIdx.x;
    if (bb < XB) {
        size_t fi = (size_t)bb * 256 + threadIdx.x;
        float4 v = *(const float4*)(x + fi * 4);
        union { __nv_bfloat16 b[4]; uint2 u; } hh, ll;
        float f[4] = {v.x, v.y, v.z, v.w};
#pragma unroll
        for (int i = 0; i < 4; i++) {
            hh.b[i] = __float2bfloat16_rn(f[i]);
            ll.b[i] = __float2bfloat16_rn(f[i] - __bfloat162float(hh.b[i]));
        }
        *(uint2*)(g_xh + fi * 4) = hh.u;
        *(uint2*)(g_xl + fi * 4) = ll.u;
    } else {
        size_t fi = (size_t)(bb - XB) * 256 + threadIdx.x;
        int g = (int)(fi >> 9);
        int c = (int)(fi & 511) * 4;
        const float* base = W + (size_t)g * WLD;

        float4 v = *(const float4*)(base + c);
        union { __nv_bfloat16 b[4]; uint2 u; } hh, ll;
        float f[4] = {v.x, v.y, v.z, v.w};
#pragma unroll
        for (int i = 0; i < 4; i++) {
            hh.b[i] = __float2bfloat16_rn(f[i]);
            ll.b[i] = __float2bfloat16_rn(f[i] - __bfloat162float(hh.b[i]));
        }
        *(uint2*)(g_wxh + (size_t)g * H_ + c) = hh.u;
        *(uint2*)(g_wxl + (size_t)g * H_ + c) = ll.u;

        v = *(const float4*)(base + H_ + c);
        float f2[4] = {v.x, v.y, v.z, v.w};
#pragma unroll
        for (int i = 0; i < 4; i++) {
            hh.b[i] = __float2bfloat16_rn(f2[i]);
            ll.b[i] = __float2bfloat16_rn(f2[i] - __bfloat162float(hh.b[i]));
        }
        *(uint2*)(g_whh + (size_t)g * H_ + c) = hh.u;
        *(uint2*)(g_whl + (size_t)g * H_ + c) = ll.u;
    }
}

// ===========================================================================
// Phase 1: u[m,g] = sum_k x[m,k] W[g,k] + b[g], 3x bf16 split mma.
// 128x128x32 tiles, 4-stage cp.async pipeline (R5 measured-best: 709us).
// ===========================================================================
#define P1_ST 40
#define P1_TILE (128 * P1_ST)
#define P1_NS 4
#define P1_SMEM_BYTES (2 * P1_NS * P1_TILE * 2)   // 81920

__global__ __launch_bounds__(256, 2)
void gemm_u_mma(const float* __restrict__ bias, float* __restrict__ out)
{
    extern __shared__ __align__(16) __nv_bfloat16 sm[];
    __nv_bfloat16* As[P1_NS];
    __nv_bfloat16* Bs[P1_NS];
#pragma unroll
    for (int s = 0; s < P1_NS; s++) {
        As[s] = sm + s * P1_TILE;
        Bs[s] = sm + (P1_NS + s) * P1_TILE;
    }

    const int tid = threadIdx.x, lane = tid & 31, wid = tid >> 5;
    const int m0 = blockIdx.y * 128, g0 = blockIdx.x * 128;
    const int wm = wid & 3, wn = wid >> 2;

    const __nv_bfloat16* Ag[3] = { g_xh, g_xh, g_xl };
    const __nv_bfloat16* Bg[3] = { g_wxh, g_wxl, g_wxh };

    const int lrow = tid >> 1;
    const int lco  = (tid & 1) * 16;

    float acc[2][8][4];
#pragma unroll
    for (int i = 0; i < 2; i++)
#pragma unroll
        for (int j = 0; j < 8; j++)
#pragma unroll
            for (int q = 0; q < 4; q++) acc[i][j][q] = 0.0f;

#define P1_ISSUE(st, it) do {                                                  \
        int _p = (it) >> 6, _kk = ((it) & 63) * 32;                            \
        const __nv_bfloat16* _ga = Ag[_p] + (size_t)(m0 + lrow) * H_ + _kk + lco; \
        const __nv_bfloat16* _gb = Bg[_p] + (size_t)(g0 + lrow) * H_ + _kk + lco; \
        uint32_t _sa = smem_u32(As[st] + lrow * P1_ST + lco);                  \
        uint32_t _sb = smem_u32(Bs[st] + lrow * P1_ST + lco);                  \
        cp16(_sa, _ga); cp16(_sa + 16, _ga + 8);                               \
        cp16(_sb, _gb); cp16(_sb + 16, _gb + 8);                               \
    } while (0)

    P1_ISSUE(0, 0); CP_COMMIT();
    P1_ISSUE(1, 1); CP_COMMIT();
    P1_ISSUE(2, 2); CP_COMMIT();

    const int NT = 192;
    for (int it = 0; it < NT; ++it) {
        asm volatile("cp.async.wait_group 2;");
        __syncthreads();
        int nx = it + 3;
        if (nx < NT) { P1_ISSUE(nx & 3, nx); }
        CP_COMMIT();

        const __nv_bfloat16* A_s = As[it & 3];
        const __nv_bfloat16* B_s = Bs[it & 3];
#pragma unroll
        for (int kq = 0; kq < 2; kq++) {
            uint32_t a[2][4];
#pragma unroll
            for (int mt = 0; mt < 2; mt++)
                ldsm4(a[mt], smem_u32(A_s + (wm * 32 + mt * 16 + (lane & 15)) * P1_ST
                                          + kq * 16 + ((lane >> 4) << 3)));
            uint32_t bf[4][4];
#pragma unroll
            for (int ng = 0; ng < 4; ng++)
                ldsm4(bf[ng], smem_u32(B_s + (wn * 64 + ng * 16 + (lane & 7) + ((lane & 16) >> 1)) * P1_ST
                                           + kq * 16 + (lane & 8)));
#pragma unroll
            for (int mt = 0; mt < 2; mt++)
#pragma unroll
                for (int ng = 0; ng < 4; ng++) {
                    mma16816(acc[mt][2 * ng],     a[mt], bf[ng][0], bf[ng][1]);
                    mma16816(acc[mt][2 * ng + 1], a[mt], bf[ng][2], bf[ng][3]);
                }
        }
    }

    const int r0 = lane >> 2, c0 = (lane & 3) * 2;
#pragma unroll
    for (int mt = 0; mt < 2; mt++) {
        int m = m0 + wm * 32 + mt * 16 + r0;
#pragma unroll
        for (int nt = 0; nt < 8; nt++) {
            int g = g0 + wn * 64 + nt * 8 + c0;
            float bx = bias[g], by = bias[g + 1];
            float2 v0 = { acc[mt][nt][0] + bx, acc[mt][nt][1] + by };
            float2 v1 = { acc[mt][nt][2] + bx, acc[mt][nt][3] + by };
            *(float2*)(out + (size_t)m * H_ + g)       = v0;
            *(float2*)(out + (size_t)(m + 8) * H_ + g) = v1;
        }
    }
}

// ===========================================================================
// Phase 2: persistent scan (R6's exact scan: cooperative-pattern barrier,
// no per-thread membar). Grid 128 = 32 g-tiles (64) x 4 k-tiles (512).
// ===========================================================================
#define GT 64
#define KT 512
#define WST 520
#define HST 520
#define O_WHH 0
#define O_WHL (GT * WST)
#define O_HH  (2 * GT * WST)
#define O_HL  (O_HH + B_ * HST)
#define SC_SMEM_ELEMS (O_HL + B_ * HST)
#define SC_SMEM_BYTES (SC_SMEM_ELEMS * 2)  // 166400

__global__ __launch_bounds__(256, 1)
void rnn_scan(float* __restrict__ out)
{
    extern __shared__ __align__(16) __nv_bfloat16 sm[];
    __nv_bfloat16* whh_s = sm + O_WHH;
    __nv_bfloat16* whl_s = sm + O_WHL;
    __nv_bfloat16* hh_s  = sm + O_HH;
    __nv_bfloat16* hl_s  = sm + O_HL;

    const int tid = threadIdx.x, lane = tid & 31, wid = tid >> 5;
    const int gi = blockIdx.x & 31;
    const int ki = blockIdx.x >> 5;
    const int g0 = gi * GT;
    const int k0 = ki * KT;

    // ---- stage Wh hi/lo slice: 64 g-rows x 512 k ----
    for (int i = tid; i < GT * (KT / 8); i += 256) {
        int row = i >> 6;
        int c8  = (i & 63) * 8;
        *(uint4*)(whh_s + row * WST + c8) =
            *(const uint4*)(g_whh + (size_t)(g0 + row) * H_ + k0 + c8);
        *(uint4*)(whl_s + row * WST + c8) =
            *(const uint4*)(g_whl + (size_t)(g0 + row) * H_ + k0 + c8);
    }
    __syncthreads();

    const int n0w = wid * 8;
    const int r0 = lane >> 2, c0 = (lane & 3) * 2;

    const uint32_t aHb = smem_u32(hh_s + (lane & 15) * HST + ((lane >> 4) << 3));
    const uint32_t aLb = smem_u32(hl_s + (lane & 15) * HST + ((lane >> 4) << 3));
    const int brow = n0w + (lane & 7);
    const int bcol = ((lane >> 3) & 3) * 8;
    const uint32_t bHb = smem_u32(whh_s + brow * WST + bcol);
    const uint32_t bLb = smem_u32(whl_s + brow * WST + bcol);

    for (int t = 1; t < T_; ++t) {
        // ---- load h_{t-1} k-slice (16 x 512 fp32), split into smem ----
#pragma unroll
        for (int r = 0; r < 8; r++) {
            int fi = tid + r * 256;
            int b  = fi >> 7;
            int c4 = fi & 127;
            float4 h4 = ld_cg4(out + (size_t)b * TH_ + (size_t)(t - 1) * H_ + k0 + c4 * 4);
            union { __nv_bfloat16 bb[4]; uint2 u; } th, tl;
            float f[4] = {h4.x, h4.y, h4.z, h4.w};
#pragma unroll
            for (int q = 0; q < 4; q++) {
                th.bb[q] = __float2bfloat16_rn(f[q]);
                tl.bb[q] = __float2bfloat16_rn(f[q] - __bfloat162float(th.bb[q]));
            }
            *(uint2*)(hh_s + b * HST + c4 * 4) = th.u;
            *(uint2*)(hl_s + b * HST + c4 * 4) = tl.u;
        }
        __syncthreads();

        // ---- compute: 16 k32 chunks, 3 accumulators ----
        float acc0[4], acc1[4], acc2[4];
#pragma unroll
        for (int q = 0; q < 4; q++) { acc0[q] = 0.0f; acc1[q] = 0.0f; acc2[q] = 0.0f; }

#pragma unroll
        for (int kc = 0; kc < 16; kc++) {
            const uint32_t off = kc * 64;
            uint32_t ah0[4], ah1[4], al0[4], al1[4], bh[4], bl[4];
            ldsm4(bh,  bHb + off);
            ldsm4(ah0, aHb + off);
            ldsm4(ah1, aHb + off + 32);
            ldsm4(bl,  bLb + off);
            ldsm4(al0, aLb + off);
            ldsm4(al1, aLb + off + 32);
            mma16816(acc0, ah0, bh[0], bh[1]);
            mma16816(acc1, ah0, bl[0], bl[1]);
            mma16816(acc2, al0, bh[0], bh[1]);
            mma16816(acc0, ah1, bh[2], bh[3]);
            mma16816(acc1, ah1, bl[2], bl[3]);
            mma16816(acc2, al1, bh[2], bh[3]);
        }

        // ---- epilogue: 4 atomic adds into out[:, t, :] (holds u_t) ----
#pragma unroll
        for (int q = 0; q < 4; q++) acc0[q] += acc1[q] + acc2[q];
        {
            float* p0 = out + (size_t)r0 * TH_ + (size_t)t * H_ + g0 + n0w + c0;
            atomicAdd(p0,     acc0[0]);
            atomicAdd(p0 + 1, acc0[1]);
            float* p1 = out + (size_t)(r0 + 8) * TH_ + (size_t)t * H_ + g0 + n0w + c0;
            atomicAdd(p1,     acc0[2]);
            atomicAdd(p1 + 1, acc0[3]);
        }

        // ---- grid barrier (cooperative-groups pattern, no per-thread fence) ----
        __syncthreads();
        if (t < T_ - 1) {
            if (tid == 0) {
                asm volatile("red.release.gpu.global.add.u32 [%0], 1;"
                             :: "l"(&g_bar[t]) : "memory");
                unsigned v;
                do {
                    asm volatile("ld.acquire.gpu.global.u32 %0, [%1];"
                                 : "=r"(v) : "l"(&g_bar[t]) : "memory");
                } while (v < NBLK);
            }
            __syncthreads();
        }
    }
}

// ---------------- h_last copy ----------------------------------------------
__global__ void hlast_kernel(const float* __restrict__ out,
                             float* __restrict__ hlast)
{
    int i = blockIdx.x * blockDim.x + threadIdx.x;
    if (i < B_ * H_) {
        int b = i / H_;
        int g = i % H_;
        hlast[i] = out[(size_t)b * TH_ + (size_t)(T_ - 1) * H_ + g];
    }
}

// ---------------- launch ----------------------------------------------------
extern "C" void kernel_launch(void* const* d_in, const int* in_sizes, int n_in,
                              void* d_out, int out_size)
{
    const float* x  = (const float*)d_in[0];
    const float* W  = (const float*)d_in[1];
    const float* bi = (const float*)d_in[2];
    float* out = (float*)d_out;

    cudaFuncSetAttribute(gemm_u_mma,
                         cudaFuncAttributeMaxDynamicSharedMemorySize,
                         P1_SMEM_BYTES);
    cudaFuncSetAttribute(rnn_scan,
                         cudaFuncAttributeMaxDynamicSharedMemorySize,
                         SC_SMEM_BYTES);

    zero_bar_kernel<<<1, T_>>>();
    split_xw_kernel<<<XB + WB, 256>>>(x, W);

    dim3 ggrid(H_ / 128, (B_ * T_) / 128);   // (16, 64)
    gemm_u_mma<<<ggrid, 256, P1_SMEM_BYTES>>>(bi, out);

    rnn_scan<<<NBLK, 256, SC_SMEM_BYTES>>>(out);

    if (out_size >= B_ * T_ * H_ + B_ * H_) {
        hlast_kernel<<<(B_ * H_ + 255) / 256, 256>>>(out, out + (size_t)B_ * T_ * H_);
    }
}

// round 11
// speedup vs baseline: 1.4010x; 1.1359x over previous
#include <cuda_runtime.h>
#include <cuda_bf16.h>
#include <cstdint>

#define B_  16
#define T_  512
#define H_  2048
#define TH_ (T_ * H_)        // 1048576
#define WLD 4096             // W row stride (floats)
#define NBLK 128

// ---------------- device globals -------------------------------------------
__device__ unsigned g_bar[T_];

__device__ __nv_bfloat16 g_xh[(size_t)B_ * T_ * H_];
__device__ __nv_bfloat16 g_xl[(size_t)B_ * T_ * H_];
__device__ __nv_bfloat16 g_wxh[(size_t)H_ * H_];
__device__ __nv_bfloat16 g_wxl[(size_t)H_ * H_];
__device__ __nv_bfloat16 g_whh[(size_t)H_ * H_];
__device__ __nv_bfloat16 g_whl[(size_t)H_ * H_];

__global__ void zero_bar_kernel() { g_bar[threadIdx.x] = 0u; }

// ---------------- helpers ---------------------------------------------------
__device__ __forceinline__ uint32_t smem_u32(const void* p) {
    return (uint32_t)__cvta_generic_to_shared(p);
}
__device__ __forceinline__ void cp16(uint32_t s, const void* g) {
    asm volatile("cp.async.cg.shared.global [%0], [%1], 16;" :: "r"(s), "l"(g));
}
#define CP_COMMIT() asm volatile("cp.async.commit_group;")

__device__ __forceinline__ void ldsm4(uint32_t (&r)[4], uint32_t addr) {
    asm volatile("ldmatrix.sync.aligned.m8n8.x4.shared.b16 {%0,%1,%2,%3}, [%4];"
                 : "=r"(r[0]), "=r"(r[1]), "=r"(r[2]), "=r"(r[3]) : "r"(addr));
}
__device__ __forceinline__ void mma16816(float (&c)[4], const uint32_t (&a)[4],
                                         uint32_t b0, uint32_t b1) {
    asm volatile("mma.sync.aligned.m16n8k16.row.col.f32.bf16.bf16.f32 "
                 "{%0,%1,%2,%3}, {%4,%5,%6,%7}, {%8,%9}, {%0,%1,%2,%3};"
                 : "+f"(c[0]), "+f"(c[1]), "+f"(c[2]), "+f"(c[3])
                 : "r"(a[0]), "r"(a[1]), "r"(a[2]), "r"(a[3]), "r"(b0), "r"(b1));
}
__device__ __forceinline__ float4 ld_cg4(const float* p) {
    float4 v;
    asm volatile("ld.global.cg.v4.f32 {%0,%1,%2,%3}, [%4];"
                 : "=f"(v.x), "=f"(v.y), "=f"(v.z), "=f"(v.w) : "l"(p));
    return v;
}
__device__ __forceinline__ void red_add_v2(float* p, float a, float b) {
    asm volatile("red.global.add.v2.f32 [%0], {%1, %2};"
                 :: "l"(p), "f"(a), "f"(b) : "memory");
}

// ---------------- prepass: hi/lo bf16 splits (one kernel) --------------------
#define XB ((B_ * T_ * H_ / 4) / 256)      // 16384
#define WB ((H_ * H_ / 4) / 256)           // 4096

__global__ void split_xw_kernel(const float* __restrict__ x,
                                const float* __restrict__ W)
{
    int bb = blockIdx.x;
    if (bb < XB) {
        size_t fi = (size_t)bb * 256 + threadIdx.x;
        float4 v = *(const float4*)(x + fi * 4);
        union { __nv_bfloat16 b[4]; uint2 u; } hh, ll;
        float f[4] = {v.x, v.y, v.z, v.w};
#pragma unroll
        for (int i = 0; i < 4; i++) {
            hh.b[i] = __float2bfloat16_rn(f[i]);
            ll.b[i] = __float2bfloat16_rn(f[i] - __bfloat162float(hh.b[i]));
        }
        *(uint2*)(g_xh + fi * 4) = hh.u;
        *(uint2*)(g_xl + fi * 4) = ll.u;
    } else {
        size_t fi = (size_t)(bb - XB) * 256 + threadIdx.x;
        int g = (int)(fi >> 9);
        int c = (int)(fi & 511) * 4;
        const float* base = W + (size_t)g * WLD;

        float4 v = *(const float4*)(base + c);
        union { __nv_bfloat16 b[4]; uint2 u; } hh, ll;
        float f[4] = {v.x, v.y, v.z, v.w};
#pragma unroll
        for (int i = 0; i < 4; i++) {
            hh.b[i] = __float2bfloat16_rn(f[i]);
            ll.b[i] = __float2bfloat16_rn(f[i] - __bfloat162float(hh.b[i]));
        }
        *(uint2*)(g_wxh + (size_t)g * H_ + c) = hh.u;
        *(uint2*)(g_wxl + (size_t)g * H_ + c) = ll.u;

        v = *(const float4*)(base + H_ + c);
        float f2[4] = {v.x, v.y, v.z, v.w};
#pragma unroll
        for (int i = 0; i < 4; i++) {
            hh.b[i] = __float2bfloat16_rn(f2[i]);
            ll.b[i] = __float2bfloat16_rn(f2[i] - __bfloat162float(hh.b[i]));
        }
        *(uint2*)(g_whh + (size_t)g * H_ + c) = hh.u;
        *(uint2*)(g_whl + (size_t)g * H_ + c) = ll.u;
    }
}

// ===========================================================================
// Phase 1: u[m,g] = sum_k x[m,k] W[g,k] + b[g], 3x bf16 split mma.
// 128x128x32 tiles, 4-stage cp.async pipeline (measured 709us).
// ===========================================================================
#define P1_ST 40
#define P1_TILE (128 * P1_ST)
#define P1_NS 4
#define P1_SMEM_BYTES (2 * P1_NS * P1_TILE * 2)   // 81920

__global__ __launch_bounds__(256, 2)
void gemm_u_mma(const float* __restrict__ bias, float* __restrict__ out)
{
    extern __shared__ __align__(16) __nv_bfloat16 sm[];
    __nv_bfloat16* As[P1_NS];
    __nv_bfloat16* Bs[P1_NS];
#pragma unroll
    for (int s = 0; s < P1_NS; s++) {
        As[s] = sm + s * P1_TILE;
        Bs[s] = sm + (P1_NS + s) * P1_TILE;
    }

    const int tid = threadIdx.x, lane = tid & 31, wid = tid >> 5;
    const int m0 = blockIdx.y * 128, g0 = blockIdx.x * 128;
    const int wm = wid & 3, wn = wid >> 2;

    const __nv_bfloat16* Ag[3] = { g_xh, g_xh, g_xl };
    const __nv_bfloat16* Bg[3] = { g_wxh, g_wxl, g_wxh };

    const int lrow = tid >> 1;
    const int lco  = (tid & 1) * 16;

    float acc[2][8][4];
#pragma unroll
    for (int i = 0; i < 2; i++)
#pragma unroll
        for (int j = 0; j < 8; j++)
#pragma unroll
            for (int q = 0; q < 4; q++) acc[i][j][q] = 0.0f;

#define P1_ISSUE(st, it) do {                                                  \
        int _p = (it) >> 6, _kk = ((it) & 63) * 32;                            \
        const __nv_bfloat16* _ga = Ag[_p] + (size_t)(m0 + lrow) * H_ + _kk + lco; \
        const __nv_bfloat16* _gb = Bg[_p] + (size_t)(g0 + lrow) * H_ + _kk + lco; \
        uint32_t _sa = smem_u32(As[st] + lrow * P1_ST + lco);                  \
        uint32_t _sb = smem_u32(Bs[st] + lrow * P1_ST + lco);                  \
        cp16(_sa, _ga); cp16(_sa + 16, _ga + 8);                               \
        cp16(_sb, _gb); cp16(_sb + 16, _gb + 8);                               \
    } while (0)

    P1_ISSUE(0, 0); CP_COMMIT();
    P1_ISSUE(1, 1); CP_COMMIT();
    P1_ISSUE(2, 2); CP_COMMIT();

    const int NT = 192;
    for (int it = 0; it < NT; ++it) {
        asm volatile("cp.async.wait_group 2;");
        __syncthreads();
        int nx = it + 3;
        if (nx < NT) { P1_ISSUE(nx & 3, nx); }
        CP_COMMIT();

        const __nv_bfloat16* A_s = As[it & 3];
        const __nv_bfloat16* B_s = Bs[it & 3];
#pragma unroll
        for (int kq = 0; kq < 2; kq++) {
            uint32_t a[2][4];
#pragma unroll
            for (int mt = 0; mt < 2; mt++)
                ldsm4(a[mt], smem_u32(A_s + (wm * 32 + mt * 16 + (lane & 15)) * P1_ST
                                          + kq * 16 + ((lane >> 4) << 3)));
            uint32_t bf[4][4];
#pragma unroll
            for (int ng = 0; ng < 4; ng++)
                ldsm4(bf[ng], smem_u32(B_s + (wn * 64 + ng * 16 + (lane & 7) + ((lane & 16) >> 1)) * P1_ST
                                           + kq * 16 + (lane & 8)));
#pragma unroll
            for (int mt = 0; mt < 2; mt++)
#pragma unroll
                for (int ng = 0; ng < 4; ng++) {
                    mma16816(acc[mt][2 * ng],     a[mt], bf[ng][0], bf[ng][1]);
                    mma16816(acc[mt][2 * ng + 1], a[mt], bf[ng][2], bf[ng][3]);
                }
        }
    }

    const int r0 = lane >> 2, c0 = (lane & 3) * 2;
#pragma unroll
    for (int mt = 0; mt < 2; mt++) {
        int m = m0 + wm * 32 + mt * 16 + r0;
#pragma unroll
        for (int nt = 0; nt < 8; nt++) {
            int g = g0 + wn * 64 + nt * 8 + c0;
            float bx = bias[g], by = bias[g + 1];
            float2 v0 = { acc[mt][nt][0] + bx, acc[mt][nt][1] + by };
            float2 v1 = { acc[mt][nt][2] + bx, acc[mt][nt][3] + by };
            *(float2*)(out + (size_t)m * H_ + g)       = v0;
            *(float2*)(out + (size_t)(m + 8) * H_ + g) = v1;
        }
    }
}

// ===========================================================================
// Phase 2: persistent scan, Wh fragments RESIDENT IN REGISTERS.
// Grid 128 = 32 g-tiles (64) x 4 k-tiles (512).
// 8 warps = 4 n-groups (n16) x 2 k-halves (k256).
// Prologue: stage Wh slice to smem, ldsm-preload each warp's B frags
// (n16 x k256 hi/lo = 128 regs/thread), then REUSE the Wh smem for h.
// Per step: h load+split (16x512) -> 8 unrolled k32 chunks (4 A-ldsm +
// 12 mma each, B from regs) -> k-half smem reduction -> kg0 warps RED ->
// global barrier (R8 pattern).
// ===========================================================================
#define GT 64
#define KT 512
#define WST 520
#define HST 520
// Wh staging occupies [0, 2*GT*WST) elems = 133120 B; after the register
// preload it is dead and h/red overlay it:
#define O_HH  0
#define O_HL  (B_ * HST)                   // 8320
#define O_RED (2 * B_ * HST)               // 16640 (elems; float area)
#define SC_SMEM_BYTES (2 * GT * WST * 2)   // 133120

__global__ __launch_bounds__(256, 1)
void rnn_scan(float* __restrict__ out)
{
    extern __shared__ __align__(16) __nv_bfloat16 sm[];
    __nv_bfloat16* whh_s = sm;                      // staging (dead after preload)
    __nv_bfloat16* whl_s = sm + GT * WST;
    __nv_bfloat16* hh_s  = sm + O_HH;               // overlays staging
    __nv_bfloat16* hl_s  = sm + O_HL;
    float* red = (float*)(sm + O_RED);              // 4 KB-ish scratch

    const int tid = threadIdx.x, lane = tid & 31, wid = tid >> 5;
    const int gi = blockIdx.x & 31;
    const int ki = blockIdx.x >> 5;
    const int g0 = gi * GT;
    const int k0 = ki * KT;

    const int wn = wid >> 1;           // n-group 0..3 (16 cols each)
    const int kg = wid & 1;            // k-half 0/1 (256 each)

    // ---- stage Wh hi/lo slice: 64 g-rows x 512 k ----
    for (int i = tid; i < GT * (KT / 8); i += 256) {
        int row = i >> 6;
        int c8  = (i & 63) * 8;
        *(uint4*)(whh_s + row * WST + c8) =
            *(const uint4*)(g_whh + (size_t)(g0 + row) * H_ + k0 + c8);
        *(uint4*)(whl_s + row * WST + c8) =
            *(const uint4*)(g_whl + (size_t)(g0 + row) * H_ + k0 + c8);
    }
    __syncthreads();

    // ---- preload B fragments into registers: n16 x k256, hi+lo ----
    uint32_t Bh[2][8][4], Bl[2][8][4];
#pragma unroll
    for (int nt = 0; nt < 2; nt++) {
        const int br = wn * 16 + nt * 8 + (lane & 7);
        const uint32_t baseH = smem_u32(whh_s + br * WST + kg * 256 + (lane >> 3) * 8);
        const uint32_t baseL = smem_u32(whl_s + br * WST + kg * 256 + (lane >> 3) * 8);
#pragma unroll
        for (int ch = 0; ch < 8; ch++) {
            ldsm4(Bh[nt][ch], baseH + ch * 64);
            ldsm4(Bl[nt][ch], baseL + ch * 64);
        }
    }
    __syncthreads();   // preload done before staging area is overwritten by h

    const int r0 = lane >> 2, c0 = (lane & 3) * 2;
    const uint32_t aHb = smem_u32(hh_s + (lane & 15) * HST + ((lane >> 4) << 3));
    const uint32_t aLb = smem_u32(hl_s + (lane & 15) * HST + ((lane >> 4) << 3));

    for (int t = 1; t < T_; ++t) {
        // ---- load h_{t-1} k-slice (16 x 512 fp32), split into smem ----
#pragma unroll
        for (int r = 0; r < 8; r++) {
            int fi = tid + r * 256;
            int b  = fi >> 7;
            int c4 = fi & 127;
            float4 h4 = ld_cg4(out + (size_t)b * TH_ + (size_t)(t - 1) * H_ + k0 + c4 * 4);
            union { __nv_bfloat16 bb[4]; uint2 u; } th, tl;
            float f[4] = {h4.x, h4.y, h4.z, h4.w};
#pragma unroll
            for (int q = 0; q < 4; q++) {
                th.bb[q] = __float2bfloat16_rn(f[q]);
                tl.bb[q] = __float2bfloat16_rn(f[q] - __bfloat162float(th.bb[q]));
            }
            *(uint2*)(hh_s + b * HST + c4 * 4) = th.u;
            *(uint2*)(hl_s + b * HST + c4 * 4) = tl.u;
        }
        __syncthreads();

        // ---- compute: 8 k32 chunks; A from smem, B from registers ----
        float accA[2][4], accB[2][4];
#pragma unroll
        for (int i = 0; i < 2; i++)
#pragma unroll
            for (int q = 0; q < 4; q++) { accA[i][q] = 0.0f; accB[i][q] = 0.0f; }

#pragma unroll
        for (int ch = 0; ch < 8; ch++) {
            const uint32_t off = kg * 512 + ch * 64;
            uint32_t ah0[4], ah1[4], al0[4], al1[4];
            ldsm4(ah0, aHb + off);
            ldsm4(ah1, aHb + off + 32);
            ldsm4(al0, aLb + off);
            ldsm4(al1, aLb + off + 32);
#pragma unroll
            for (int nt = 0; nt < 2; nt++) {
                mma16816(accA[nt], ah0, Bh[nt][ch][0], Bh[nt][ch][1]);
                mma16816(accA[nt], ah1, Bh[nt][ch][2], Bh[nt][ch][3]);
                mma16816(accB[nt], ah0, Bl[nt][ch][0], Bl[nt][ch][1]);
                mma16816(accB[nt], ah1, Bl[nt][ch][2], Bl[nt][ch][3]);
                mma16816(accB[nt], al0, Bh[nt][ch][0], Bh[nt][ch][1]);
                mma16816(accB[nt], al1, Bh[nt][ch][2], Bh[nt][ch][3]);
            }
        }
        __syncthreads();   // everyone done reading hh_s/hl_s (and prior red use)

        // ---- k-half reduction via smem: kg=1 stores, kg=0 adds ----
        float* rw = red + (wn * 32 + lane) * 8;
        if (kg == 1) {
#pragma unroll
            for (int nt = 0; nt < 2; nt++) {
                float4 v = { accA[nt][0] + accB[nt][0], accA[nt][1] + accB[nt][1],
                             accA[nt][2] + accB[nt][2], accA[nt][3] + accB[nt][3] };
                *(float4*)(rw + nt * 4) = v;
            }
        }
        __syncthreads();

        if (kg == 0) {
#pragma unroll
            for (int nt = 0; nt < 2; nt++) {
                float4 v = *(const float4*)(rw + nt * 4);
                float s0 = accA[nt][0] + accB[nt][0] + v.x;
                float s1 = accA[nt][1] + accB[nt][1] + v.y;
                float s2 = accA[nt][2] + accB[nt][2] + v.z;
                float s3 = accA[nt][3] + accB[nt][3] + v.w;
                const int gcol = g0 + wn * 16 + nt * 8 + c0;
                red_add_v2(out + (size_t)r0 * TH_ + (size_t)t * H_ + gcol, s0, s1);
                red_add_v2(out + (size_t)(r0 + 8) * TH_ + (size_t)t * H_ + gcol, s2, s3);
            }
        }

        // ---- grid barrier (R8 pattern) ----
        __syncthreads();
        if (t < T_ - 1) {
            if (tid == 0) {
                asm volatile("red.release.gpu.global.add.u32 [%0], 1;"
                             :: "l"(&g_bar[t]) : "memory");
                unsigned v;
                do {
                    asm volatile("ld.acquire.gpu.global.u32 %0, [%1];"
                                 : "=r"(v) : "l"(&g_bar[t]) : "memory");
                } while (v < NBLK);
            }
            __syncthreads();
        }
    }
}

// ---------------- h_last copy ----------------------------------------------
__global__ void hlast_kernel(const float* __restrict__ out,
                             float* __restrict__ hlast)
{
    int i = blockIdx.x * blockDim.x + threadIdx.x;
    if (i < B_ * H_) {
        int b = i / H_;
        int g = i % H_;
        hlast[i] = out[(size_t)b * TH_ + (size_t)(T_ - 1) * H_ + g];
    }
}

// ---------------- launch ----------------------------------------------------
extern "C" void kernel_launch(void* const* d_in, const int* in_sizes, int n_in,
                              void* d_out, int out_size)
{
    const float* x  = (const float*)d_in[0];
    const float* W  = (const float*)d_in[1];
    const float* bi = (const float*)d_in[2];
    float* out = (float*)d_out;

    cudaFuncSetAttribute(gemm_u_mma,
                         cudaFuncAttributeMaxDynamicSharedMemorySize,
                         P1_SMEM_BYTES);
    cudaFuncSetAttribute(rnn_scan,
                         cudaFuncAttributeMaxDynamicSharedMemorySize,
                         SC_SMEM_BYTES);

    zero_bar_kernel<<<1, T_>>>();
    split_xw_kernel<<<XB + WB, 256>>>(x, W);

    dim3 ggrid(H_ / 128, (B_ * T_) / 128);   // (16, 64)
    gemm_u_mma<<<ggrid, 256, P1_SMEM_BYTES>>>(bi, out);

    rnn_scan<<<NBLK, 256, SC_SMEM_BYTES>>>(out);

    if (out_size >= B_ * T_ * H_ + B_ * H_) {
        hlast_kernel<<<(B_ * H_ + 255) / 256, 256>>>(out, out + (size_t)B_ * T_ * H_);
    }
}

// round 12
// speedup vs baseline: 1.5210x; 1.0856x over previous
#include <cuda_runtime.h>
#include <cuda_bf16.h>
#include <cstdint>

#define B_  16
#define T_  512
#define H_  2048
#define TH_ (T_ * H_)        // 1048576
#define WLD 4096             // W row stride (floats)
#define NBLK 128

// ---------------- device globals -------------------------------------------
// 4 sub-barriers: bar2[q][t] counts arrivals of the 32 blocks whose g-tile
// feeds k-slice q. Producer (gi,ki) arrives at q = gi>>3; consumer waits on
// its own ki. One poll address per block per step.
__device__ unsigned g_bar2[4 * T_];

__device__ __nv_bfloat16 g_xh[(size_t)B_ * T_ * H_];
__device__ __nv_bfloat16 g_xl[(size_t)B_ * T_ * H_];
__device__ __nv_bfloat16 g_wxh[(size_t)H_ * H_];
__device__ __nv_bfloat16 g_wxl[(size_t)H_ * H_];
__device__ __nv_bfloat16 g_whh[(size_t)H_ * H_];
__device__ __nv_bfloat16 g_whl[(size_t)H_ * H_];

__global__ void zero_bar_kernel() {
    int i = blockIdx.x * blockDim.x + threadIdx.x;
    if (i < 4 * T_) g_bar2[i] = 0u;
}

// ---------------- helpers ---------------------------------------------------
__device__ __forceinline__ uint32_t smem_u32(const void* p) {
    return (uint32_t)__cvta_generic_to_shared(p);
}
__device__ __forceinline__ void cp16(uint32_t s, const void* g) {
    asm volatile("cp.async.cg.shared.global [%0], [%1], 16;" :: "r"(s), "l"(g));
}
#define CP_COMMIT() asm volatile("cp.async.commit_group;")

__device__ __forceinline__ void ldsm4(uint32_t (&r)[4], uint32_t addr) {
    asm volatile("ldmatrix.sync.aligned.m8n8.x4.shared.b16 {%0,%1,%2,%3}, [%4];"
                 : "=r"(r[0]), "=r"(r[1]), "=r"(r[2]), "=r"(r[3]) : "r"(addr));
}
__device__ __forceinline__ void mma16816(float (&c)[4], const uint32_t (&a)[4],
                                         uint32_t b0, uint32_t b1) {
    asm volatile("mma.sync.aligned.m16n8k16.row.col.f32.bf16.bf16.f32 "
                 "{%0,%1,%2,%3}, {%4,%5,%6,%7}, {%8,%9}, {%0,%1,%2,%3};"
                 : "+f"(c[0]), "+f"(c[1]), "+f"(c[2]), "+f"(c[3])
                 : "r"(a[0]), "r"(a[1]), "r"(a[2]), "r"(a[3]), "r"(b0), "r"(b1));
}
__device__ __forceinline__ float4 ld_cg4(const float* p) {
    float4 v;
    asm volatile("ld.global.cg.v4.f32 {%0,%1,%2,%3}, [%4];"
                 : "=f"(v.x), "=f"(v.y), "=f"(v.z), "=f"(v.w) : "l"(p));
    return v;
}
__device__ __forceinline__ void red_add_v2(float* p, float a, float b) {
    asm volatile("red.global.add.v2.f32 [%0], {%1, %2};"
                 :: "l"(p), "f"(a), "f"(b) : "memory");
}

// ---------------- prepass: hi/lo bf16 splits (one kernel) --------------------
#define XB ((B_ * T_ * H_ / 4) / 256)      // 16384
#define WB ((H_ * H_ / 4) / 256)           // 4096

__global__ void split_xw_kernel(const float* __restrict__ x,
                                const float* __restrict__ W)
{
    int bb = blockIdx.x;
    if (bb < XB) {
        size_t fi = (size_t)bb * 256 + threadIdx.x;
        float4 v = *(const float4*)(x + fi * 4);
        union { __nv_bfloat16 b[4]; uint2 u; } hh, ll;
        float f[4] = {v.x, v.y, v.z, v.w};
#pragma unroll
        for (int i = 0; i < 4; i++) {
            hh.b[i] = __float2bfloat16_rn(f[i]);
            ll.b[i] = __float2bfloat16_rn(f[i] - __bfloat162float(hh.b[i]));
        }
        *(uint2*)(g_xh + fi * 4) = hh.u;
        *(uint2*)(g_xl + fi * 4) = ll.u;
    } else {
        size_t fi = (size_t)(bb - XB) * 256 + threadIdx.x;
        int g = (int)(fi >> 9);
        int c = (int)(fi & 511) * 4;
        const float* base = W + (size_t)g * WLD;

        float4 v = *(const float4*)(base + c);
        union { __nv_bfloat16 b[4]; uint2 u; } hh, ll;
        float f[4] = {v.x, v.y, v.z, v.w};
#pragma unroll
        for (int i = 0; i < 4; i++) {
            hh.b[i] = __float2bfloat16_rn(f[i]);
            ll.b[i] = __float2bfloat16_rn(f[i] - __bfloat162float(hh.b[i]));
        }
        *(uint2*)(g_wxh + (size_t)g * H_ + c) = hh.u;
        *(uint2*)(g_wxl + (size_t)g * H_ + c) = ll.u;

        v = *(const float4*)(base + H_ + c);
        float f2[4] = {v.x, v.y, v.z, v.w};
#pragma unroll
        for (int i = 0; i < 4; i++) {
            hh.b[i] = __float2bfloat16_rn(f2[i]);
            ll.b[i] = __float2bfloat16_rn(f2[i] - __bfloat162float(hh.b[i]));
        }
        *(uint2*)(g_whh + (size_t)g * H_ + c) = hh.u;
        *(uint2*)(g_whl + (size_t)g * H_ + c) = ll.u;
    }
}

// ===========================================================================
// Phase 1: u[m,g] = sum_k x[m,k] W[g,k] + b[g], 3x bf16 split mma.
// 128x128x32 tiles, 4-stage cp.async pipeline (measured 709us).
// ===========================================================================
#define P1_ST 40
#define P1_TILE (128 * P1_ST)
#define P1_NS 4
#define P1_SMEM_BYTES (2 * P1_NS * P1_TILE * 2)   // 81920

__global__ __launch_bounds__(256, 2)
void gemm_u_mma(const float* __restrict__ bias, float* __restrict__ out)
{
    extern __shared__ __align__(16) __nv_bfloat16 sm[];
    __nv_bfloat16* As[P1_NS];
    __nv_bfloat16* Bs[P1_NS];
#pragma unroll
    for (int s = 0; s < P1_NS; s++) {
        As[s] = sm + s * P1_TILE;
        Bs[s] = sm + (P1_NS + s) * P1_TILE;
    }

    const int tid = threadIdx.x, lane = tid & 31, wid = tid >> 5;
    const int m0 = blockIdx.y * 128, g0 = blockIdx.x * 128;
    const int wm = wid & 3, wn = wid >> 2;

    const __nv_bfloat16* Ag[3] = { g_xh, g_xh, g_xl };
    const __nv_bfloat16* Bg[3] = { g_wxh, g_wxl, g_wxh };

    const int lrow = tid >> 1;
    const int lco  = (tid & 1) * 16;

    float acc[2][8][4];
#pragma unroll
    for (int i = 0; i < 2; i++)
#pragma unroll
        for (int j = 0; j < 8; j++)
#pragma unroll
            for (int q = 0; q < 4; q++) acc[i][j][q] = 0.0f;

#define P1_ISSUE(st, it) do {                                                  \
        int _p = (it) >> 6, _kk = ((it) & 63) * 32;                            \
        const __nv_bfloat16* _ga = Ag[_p] + (size_t)(m0 + lrow) * H_ + _kk + lco; \
        const __nv_bfloat16* _gb = Bg[_p] + (size_t)(g0 + lrow) * H_ + _kk + lco; \
        uint32_t _sa = smem_u32(As[st] + lrow * P1_ST + lco);                  \
        uint32_t _sb = smem_u32(Bs[st] + lrow * P1_ST + lco);                  \
        cp16(_sa, _ga); cp16(_sa + 16, _ga + 8);                               \
        cp16(_sb, _gb); cp16(_sb + 16, _gb + 8);                               \
    } while (0)

    P1_ISSUE(0, 0); CP_COMMIT();
    P1_ISSUE(1, 1); CP_COMMIT();
    P1_ISSUE(2, 2); CP_COMMIT();

    const int NT = 192;
    for (int it = 0; it < NT; ++it) {
        asm volatile("cp.async.wait_group 2;");
        __syncthreads();
        int nx = it + 3;
        if (nx < NT) { P1_ISSUE(nx & 3, nx); }
        CP_COMMIT();

        const __nv_bfloat16* A_s = As[it & 3];
        const __nv_bfloat16* B_s = Bs[it & 3];
#pragma unroll
        for (int kq = 0; kq < 2; kq++) {
            uint32_t a[2][4];
#pragma unroll
            for (int mt = 0; mt < 2; mt++)
                ldsm4(a[mt], smem_u32(A_s + (wm * 32 + mt * 16 + (lane & 15)) * P1_ST
                                          + kq * 16 + ((lane >> 4) << 3)));
            uint32_t bf[4][4];
#pragma unroll
            for (int ng = 0; ng < 4; ng++)
                ldsm4(bf[ng], smem_u32(B_s + (wn * 64 + ng * 16 + (lane & 7) + ((lane & 16) >> 1)) * P1_ST
                                           + kq * 16 + (lane & 8)));
#pragma unroll
            for (int mt = 0; mt < 2; mt++)
#pragma unroll
                for (int ng = 0; ng < 4; ng++) {
                    mma16816(acc[mt][2 * ng],     a[mt], bf[ng][0], bf[ng][1]);
                    mma16816(acc[mt][2 * ng + 1], a[mt], bf[ng][2], bf[ng][3]);
                }
        }
    }

    const int r0 = lane >> 2, c0 = (lane & 3) * 2;
#pragma unroll
    for (int mt = 0; mt < 2; mt++) {
        int m = m0 + wm * 32 + mt * 16 + r0;
#pragma unroll
        for (int nt = 0; nt < 8; nt++) {
            int g = g0 + wn * 64 + nt * 8 + c0;
            float bx = bias[g], by = bias[g + 1];
            float2 v0 = { acc[mt][nt][0] + bx, acc[mt][nt][1] + by };
            float2 v1 = { acc[mt][nt][2] + bx, acc[mt][nt][3] + by };
            *(float2*)(out + (size_t)m * H_ + g)       = v0;
            *(float2*)(out + (size_t)(m + 8) * H_ + g) = v1;
        }
    }
}

// ===========================================================================
// Phase 2: persistent scan, Wh in registers, 4-group sub-barriers.
// Grid 128 = 32 g-tiles (64) x 4 k-tiles (512).
// 8 warps = 4 n-groups (n16) x 2 k-halves (k256).
// Producer (gi,ki) arrives at bar2[gi>>3][t]; consumer waits bar2[ki][t-1]>=32.
// ===========================================================================
#define GT 64
#define KT 512
#define WST 520
#define HST 520
#define O_HH  0
#define O_HL  (B_ * HST)                   // 8320
#define O_RED (2 * B_ * HST)               // 16640 (elems; float area)
#define SC_SMEM_BYTES (2 * GT * WST * 2)   // 133120

__global__ __launch_bounds__(256, 1)
void rnn_scan(float* __restrict__ out)
{
    extern __shared__ __align__(16) __nv_bfloat16 sm[];
    __nv_bfloat16* whh_s = sm;                      // staging (dead after preload)
    __nv_bfloat16* whl_s = sm + GT * WST;
    __nv_bfloat16* hh_s  = sm + O_HH;               // overlays staging
    __nv_bfloat16* hl_s  = sm + O_HL;
    float* red = (float*)(sm + O_RED);

    const int tid = threadIdx.x, lane = tid & 31, wid = tid >> 5;
    const int gi = blockIdx.x & 31;
    const int ki = blockIdx.x >> 5;
    const int g0 = gi * GT;
    const int k0 = ki * KT;

    const int wn = wid >> 1;           // n-group 0..3 (16 cols each)
    const int kg = wid & 1;            // k-half 0/1 (256 each)

    // ---- stage Wh hi/lo slice: 64 g-rows x 512 k ----
    for (int i = tid; i < GT * (KT / 8); i += 256) {
        int row = i >> 6;
        int c8  = (i & 63) * 8;
        *(uint4*)(whh_s + row * WST + c8) =
            *(const uint4*)(g_whh + (size_t)(g0 + row) * H_ + k0 + c8);
        *(uint4*)(whl_s + row * WST + c8) =
            *(const uint4*)(g_whl + (size_t)(g0 + row) * H_ + k0 + c8);
    }
    __syncthreads();

    // ---- preload B fragments into registers: n16 x k256, hi+lo ----
    uint32_t Bh[2][8][4], Bl[2][8][4];
#pragma unroll
    for (int nt = 0; nt < 2; nt++) {
        const int br = wn * 16 + nt * 8 + (lane & 7);
        const uint32_t baseH = smem_u32(whh_s + br * WST + kg * 256 + (lane >> 3) * 8);
        const uint32_t baseL = smem_u32(whl_s + br * WST + kg * 256 + (lane >> 3) * 8);
#pragma unroll
        for (int ch = 0; ch < 8; ch++) {
            ldsm4(Bh[nt][ch], baseH + ch * 64);
            ldsm4(Bl[nt][ch], baseL + ch * 64);
        }
    }
    __syncthreads();   // preload done before staging area is overwritten by h

    const int r0 = lane >> 2, c0 = (lane & 3) * 2;
    const uint32_t aHb = smem_u32(hh_s + (lane & 15) * HST + ((lane >> 4) << 3));
    const uint32_t aLb = smem_u32(hl_s + (lane & 15) * HST + ((lane >> 4) << 3));

    unsigned* mybar = &g_bar2[(gi >> 3) * T_];   // producer side
    unsigned* wtbar = &g_bar2[ki * T_];          // consumer side

    for (int t = 1; t < T_; ++t) {
        // ---- wait: my k-slice of h_{t-1} complete (32 producers) ----
        if (t >= 2) {
            if (tid == 0) {
                unsigned v;
                do {
                    asm volatile("ld.acquire.gpu.global.u32 %0, [%1];"
                                 : "=r"(v) : "l"(wtbar + (t - 1)) : "memory");
                } while (v < 32u);
            }
            __syncthreads();
        }

        // ---- load h_{t-1} k-slice (16 x 512 fp32), split into smem ----
#pragma unroll
        for (int r = 0; r < 8; r++) {
            int fi = tid + r * 256;
            int b  = fi >> 7;
            int c4 = fi & 127;
            float4 h4 = ld_cg4(out + (size_t)b * TH_ + (size_t)(t - 1) * H_ + k0 + c4 * 4);
            union { __nv_bfloat16 bb[4]; uint2 u; } th, tl;
            float f[4] = {h4.x, h4.y, h4.z, h4.w};
#pragma unroll
            for (int q = 0; q < 4; q++) {
                th.bb[q] = __float2bfloat16_rn(f[q]);
                tl.bb[q] = __float2bfloat16_rn(f[q] - __bfloat162float(th.bb[q]));
            }
            *(uint2*)(hh_s + b * HST + c4 * 4) = th.u;
            *(uint2*)(hl_s + b * HST + c4 * 4) = tl.u;
        }
        __syncthreads();

        // ---- compute: 8 k32 chunks; A from smem, B from registers ----
        float accA[2][4], accB[2][4];
#pragma unroll
        for (int i = 0; i < 2; i++)
#pragma unroll
            for (int q = 0; q < 4; q++) { accA[i][q] = 0.0f; accB[i][q] = 0.0f; }

#pragma unroll
        for (int ch = 0; ch < 8; ch++) {
            const uint32_t off = kg * 512 + ch * 64;
            uint32_t ah0[4], ah1[4], al0[4], al1[4];
            ldsm4(ah0, aHb + off);
            ldsm4(ah1, aHb + off + 32);
            ldsm4(al0, aLb + off);
            ldsm4(al1, aLb + off + 32);
#pragma unroll
            for (int nt = 0; nt < 2; nt++) {
                mma16816(accA[nt], ah0, Bh[nt][ch][0], Bh[nt][ch][1]);
                mma16816(accA[nt], ah1, Bh[nt][ch][2], Bh[nt][ch][3]);
                mma16816(accB[nt], ah0, Bl[nt][ch][0], Bl[nt][ch][1]);
                mma16816(accB[nt], ah1, Bl[nt][ch][2], Bl[nt][ch][3]);
                mma16816(accB[nt], al0, Bh[nt][ch][0], Bh[nt][ch][1]);
                mma16816(accB[nt], al1, Bh[nt][ch][2], Bh[nt][ch][3]);
            }
        }

        // ---- k-half reduction via smem: kg=1 stores right away ----
        // (WAR on red vs previous step's kg0 reads is covered by the
        //  step-boundary syncs; kg0 readers wait at the sync below.)
        float* rw = red + (wn * 32 + lane) * 8;
        if (kg == 1) {
#pragma unroll
            for (int nt = 0; nt < 2; nt++) {
                float4 v = { accA[nt][0] + accB[nt][0], accA[nt][1] + accB[nt][1],
                             accA[nt][2] + accB[nt][2], accA[nt][3] + accB[nt][3] };
                *(float4*)(rw + nt * 4) = v;
            }
        }
        __syncthreads();

        if (kg == 0) {
#pragma unroll
            for (int nt = 0; nt < 2; nt++) {
                float4 v = *(const float4*)(rw + nt * 4);
                float s0 = accA[nt][0] + accB[nt][0] + v.x;
                float s1 = accA[nt][1] + accB[nt][1] + v.y;
                float s2 = accA[nt][2] + accB[nt][2] + v.z;
                float s3 = accA[nt][3] + accB[nt][3] + v.w;
                const int gcol = g0 + wn * 16 + nt * 8 + c0;
                red_add_v2(out + (size_t)r0 * TH_ + (size_t)t * H_ + gcol, s0, s1);
                red_add_v2(out + (size_t)(r0 + 8) * TH_ + (size_t)t * H_ + gcol, s2, s3);
            }
        }

        // ---- publish: arrive at my g-group's counter for step t ----
        __syncthreads();              // all CTA REDs issued before the release
        if (t < T_ - 1 && tid == 0) {
            asm volatile("red.release.gpu.global.add.u32 [%0], 1;"
                         :: "l"(mybar + t) : "memory");
        }
    }
}

// ---------------- h_last copy ----------------------------------------------
__global__ void hlast_kernel(const float* __restrict__ out,
                             float* __restrict__ hlast)
{
    int i = blockIdx.x * blockDim.x + threadIdx.x;
    if (i < B_ * H_) {
        int b = i / H_;
        int g = i % H_;
        hlast[i] = out[(size_t)b * TH_ + (size_t)(T_ - 1) * H_ + g];
    }
}

// ---------------- launch ----------------------------------------------------
extern "C" void kernel_launch(void* const* d_in, const int* in_sizes, int n_in,
                              void* d_out, int out_size)
{
    const float* x  = (const float*)d_in[0];
    const float* W  = (const float*)d_in[1];
    const float* bi = (const float*)d_in[2];
    float* out = (float*)d_out;

    cudaFuncSetAttribute(gemm_u_mma,
                         cudaFuncAttributeMaxDynamicSharedMemorySize,
                         P1_SMEM_BYTES);
    cudaFuncSetAttribute(rnn_scan,
                         cudaFuncAttributeMaxDynamicSharedMemorySize,
                         SC_SMEM_BYTES);

    zero_bar_kernel<<<(4 * T_ + 255) / 256, 256>>>();
    split_xw_kernel<<<XB + WB, 256>>>(x, W);

    dim3 ggrid(H_ / 128, (B_ * T_) / 128);   // (16, 64)
    gemm_u_mma<<<ggrid, 256, P1_SMEM_BYTES>>>(bi, out);

    rnn_scan<<<NBLK, 256, SC_SMEM_BYTES>>>(out);

    if (out_size >= B_ * T_ * H_ + B_ * H_) {
        hlast_kernel<<<(B_ * H_ + 255) / 256, 256>>>(out, out + (size_t)B_ * T_ * H_);
    }
}

// round 14
// speedup vs baseline: 1.5956x; 1.0491x over previous
#include <cuda_runtime.h>
#include <cuda_bf16.h>
#include <cstdint>

#define B_  16
#define T_  512
#define H_  2048
#define TH_ (T_ * H_)        // 1048576
#define WLD 4096             // W row stride (floats)
#define NBLK 128

// ---------------- device globals -------------------------------------------
__device__ unsigned g_bar2[4 * T_];

__device__ __nv_bfloat16 g_xh[(size_t)B_ * T_ * H_];
__device__ __nv_bfloat16 g_xl[(size_t)B_ * T_ * H_];
__device__ __nv_bfloat16 g_wxh[(size_t)H_ * H_];
__device__ __nv_bfloat16 g_wxl[(size_t)H_ * H_];
__device__ __nv_bfloat16 g_whh[(size_t)H_ * H_];
__device__ __nv_bfloat16 g_whl[(size_t)H_ * H_];

__global__ void zero_bar_kernel() {
    int i = blockIdx.x * blockDim.x + threadIdx.x;
    if (i < 4 * T_) g_bar2[i] = 0u;
}

// ---------------- helpers ---------------------------------------------------
__device__ __forceinline__ uint32_t smem_u32(const void* p) {
    return (uint32_t)__cvta_generic_to_shared(p);
}
__device__ __forceinline__ void cp16(uint32_t s, const void* g) {
    asm volatile("cp.async.cg.shared.global [%0], [%1], 16;" :: "r"(s), "l"(g));
}
#define CP_COMMIT() asm volatile("cp.async.commit_group;")

__device__ __forceinline__ void ldsm4(uint32_t (&r)[4], uint32_t addr) {
    asm volatile("ldmatrix.sync.aligned.m8n8.x4.shared.b16 {%0,%1,%2,%3}, [%4];"
                 : "=r"(r[0]), "=r"(r[1]), "=r"(r[2]), "=r"(r[3]) : "r"(addr));
}
__device__ __forceinline__ void mma16816(float (&c)[4], const uint32_t (&a)[4],
                                         uint32_t b0, uint32_t b1) {
    asm volatile("mma.sync.aligned.m16n8k16.row.col.f32.bf16.bf16.f32 "
                 "{%0,%1,%2,%3}, {%4,%5,%6,%7}, {%8,%9}, {%0,%1,%2,%3};"
                 : "+f"(c[0]), "+f"(c[1]), "+f"(c[2]), "+f"(c[3])
                 : "r"(a[0]), "r"(a[1]), "r"(a[2]), "r"(a[3]), "r"(b0), "r"(b1));
}
__device__ __forceinline__ float4 ld_cg4(const float* p) {
    float4 v;
    asm volatile("ld.global.cg.v4.f32 {%0,%1,%2,%3}, [%4];"
                 : "=f"(v.x), "=f"(v.y), "=f"(v.z), "=f"(v.w) : "l"(p));
    return v;
}
__device__ __forceinline__ void red_add_v2(float* p, float a, float b) {
    asm volatile("red.global.add.v2.f32 [%0], {%1, %2};"
                 :: "l"(p), "f"(a), "f"(b) : "memory");
}

// ---------------- prepass: hi/lo bf16 splits (one kernel) --------------------
#define XB ((B_ * T_ * H_ / 4) / 256)      // 16384
#define WB ((H_ * H_ / 4) / 256)           // 4096

__global__ void split_xw_kernel(const float* __restrict__ x,
                                const float* __restrict__ W)
{
    int bb = blockIdx.x;
    if (bb < XB) {
        size_t fi = (size_t)bb * 256 + threadIdx.x;
        float4 v = *(const float4*)(x + fi * 4);
        union { __nv_bfloat16 b[4]; uint2 u; } hh, ll;
        float f[4] = {v.x, v.y, v.z, v.w};
#pragma unroll
        for (int i = 0; i < 4; i++) {
            hh.b[i] = __float2bfloat16_rn(f[i]);
            ll.b[i] = __float2bfloat16_rn(f[i] - __bfloat162float(hh.b[i]));
        }
        *(uint2*)(g_xh + fi * 4) = hh.u;
        *(uint2*)(g_xl + fi * 4) = ll.u;
    } else {
        size_t fi = (size_t)(bb - XB) * 256 + threadIdx.x;
        int g = (int)(fi >> 9);
        int c = (int)(fi & 511) * 4;
        const float* base = W + (size_t)g * WLD;

        float4 v = *(const float4*)(base + c);
        union { __nv_bfloat16 b[4]; uint2 u; } hh, ll;
        float f[4] = {v.x, v.y, v.z, v.w};
#pragma unroll
        for (int i = 0; i < 4; i++) {
            hh.b[i] = __float2bfloat16_rn(f[i]);
            ll.b[i] = __float2bfloat16_rn(f[i] - __bfloat162float(hh.b[i]));
        }
        *(uint2*)(g_wxh + (size_t)g * H_ + c) = hh.u;
        *(uint2*)(g_wxl + (size_t)g * H_ + c) = ll.u;

        v = *(const float4*)(base + H_ + c);
        float f2[4] = {v.x, v.y, v.z, v.w};
#pragma unroll
        for (int i = 0; i < 4; i++) {
            hh.b[i] = __float2bfloat16_rn(f2[i]);
            ll.b[i] = __float2bfloat16_rn(f2[i] - __bfloat162float(hh.b[i]));
        }
        *(uint2*)(g_whh + (size_t)g * H_ + c) = hh.u;
        *(uint2*)(g_whl + (size_t)g * H_ + c) = ll.u;
    }
}

// ===========================================================================
// Phase 1: u[m,g] = sum_k x[m,k] W[g,k] + b[g], FUSED 3x bf16 split mma.
// 128x128x32 tiles; per chunk load Ah/Al/Bh/Bl once, issue all 3 products.
// 2 stages x 4 tiles (80 KB), occupancy 2, 64 iterations.
// ===========================================================================
#define P1_ST 40
#define P1_TILE (128 * P1_ST)              // elems per tile
#define P1_STAGE (4 * P1_TILE)             // Ah,Al,Bh,Bl
#define P1_SMEM_BYTES (2 * P1_STAGE * 2)   // 81920

__global__ __launch_bounds__(256, 2)
void gemm_u_mma(const float* __restrict__ bias, float* __restrict__ out)
{
    extern __shared__ __align__(16) __nv_bfloat16 sm[];

    const int tid = threadIdx.x, lane = tid & 31, wid = tid >> 5;
    const int m0 = blockIdx.y * 128, g0 = blockIdx.x * 128;
    const int wm = wid & 3, wn = wid >> 2;

    const int lrow = tid >> 1;
    const int lco  = (tid & 1) * 16;

    float acc[2][8][4];
#pragma unroll
    for (int i = 0; i < 2; i++)
#pragma unroll
        for (int j = 0; j < 8; j++)
#pragma unroll
            for (int q = 0; q < 4; q++) acc[i][j][q] = 0.0f;

#define P1F_ISSUE(st, it) do {                                                 \
        int _kk = (it) * 32;                                                   \
        __nv_bfloat16* _s = sm + (st) * P1_STAGE;                              \
        uint32_t _sa = smem_u32(_s + lrow * P1_ST + lco);                      \
        const __nv_bfloat16* _g;                                               \
        _g = g_xh  + (size_t)(m0 + lrow) * H_ + _kk + lco;                     \
        cp16(_sa, _g); cp16(_sa + 16, _g + 8);                                 \
        _g = g_xl  + (size_t)(m0 + lrow) * H_ + _kk + lco;                     \
        cp16(_sa + 2 * P1_TILE, _g); cp16(_sa + 2 * P1_TILE + 16, _g + 8);     \
        _g = g_wxh + (size_t)(g0 + lrow) * H_ + _kk + lco;                     \
        cp16(_sa + 4 * P1_TILE, _g); cp16(_sa + 4 * P1_TILE + 16, _g + 8);     \
        _g = g_wxl + (size_t)(g0 + lrow) * H_ + _kk + lco;                     \
        cp16(_sa + 6 * P1_TILE, _g); cp16(_sa + 6 * P1_TILE + 16, _g + 8);     \
    } while (0)

    P1F_ISSUE(0, 0); CP_COMMIT();

    const int NT = 64;
    for (int it = 0; it < NT; ++it) {
        if (it + 1 < NT) {
            P1F_ISSUE((it + 1) & 1, it + 1); CP_COMMIT();
            asm volatile("cp.async.wait_group 1;");
        } else {
            asm volatile("cp.async.wait_group 0;");
        }
        __syncthreads();

        const __nv_bfloat16* S  = sm + (it & 1) * P1_STAGE;
        const __nv_bfloat16* Ah = S;
        const __nv_bfloat16* Al = S + P1_TILE;
        const __nv_bfloat16* Bh = S + 2 * P1_TILE;
        const __nv_bfloat16* Bl = S + 3 * P1_TILE;

#pragma unroll
        for (int kq = 0; kq < 2; kq++) {
            const int arow = wm * 32 + (lane & 15);
            const int acol = kq * 16 + ((lane >> 4) << 3);
            const int brow = wn * 64 + (lane & 7) + ((lane & 16) >> 1);
            const int bcol = kq * 16 + (lane & 8);

            uint32_t ah[2][4], al[2][4];
#pragma unroll
            for (int mt = 0; mt < 2; mt++) {
                ldsm4(ah[mt], smem_u32(Ah + (arow + mt * 16) * P1_ST + acol));
                ldsm4(al[mt], smem_u32(Al + (arow + mt * 16) * P1_ST + acol));
            }
            // ---- B-hi: AhBh + AlBh ----
            {
                uint32_t bf[4][4];
#pragma unroll
                for (int ng = 0; ng < 4; ng++)
                    ldsm4(bf[ng], smem_u32(Bh + (brow + ng * 16) * P1_ST + bcol));
#pragma unroll
                for (int mt = 0; mt < 2; mt++)
#pragma unroll
                    for (int ng = 0; ng < 4; ng++) {
                        mma16816(acc[mt][2 * ng],     ah[mt], bf[ng][0], bf[ng][1]);
                        mma16816(acc[mt][2 * ng + 1], ah[mt], bf[ng][2], bf[ng][3]);
                        mma16816(acc[mt][2 * ng],     al[mt], bf[ng][0], bf[ng][1]);
                        mma16816(acc[mt][2 * ng + 1], al[mt], bf[ng][2], bf[ng][3]);
                    }
            }
            // ---- B-lo: AhBl ----
            {
                uint32_t bf[4][4];
#pragma unroll
                for (int ng = 0; ng < 4; ng++)
                    ldsm4(bf[ng], smem_u32(Bl + (brow + ng * 16) * P1_ST + bcol));
#pragma unroll
                for (int mt = 0; mt < 2; mt++)
#pragma unroll
                    for (int ng = 0; ng < 4; ng++) {
                        mma16816(acc[mt][2 * ng],     ah[mt], bf[ng][0], bf[ng][1]);
                        mma16816(acc[mt][2 * ng + 1], ah[mt], bf[ng][2], bf[ng][3]);
                    }
            }
        }
        __syncthreads();
    }

    const int r0 = lane >> 2, c0 = (lane & 3) * 2;
#pragma unroll
    for (int mt = 0; mt < 2; mt++) {
        int m = m0 + wm * 32 + mt * 16 + r0;
#pragma unroll
        for (int nt = 0; nt < 8; nt++) {
            int g = g0 + wn * 64 + nt * 8 + c0;
            float bx = bias[g], by = bias[g + 1];
            float2 v0 = { acc[mt][nt][0] + bx, acc[mt][nt][1] + by };
            float2 v1 = { acc[mt][nt][2] + bx, acc[mt][nt][3] + by };
            *(float2*)(out + (size_t)m * H_ + g)       = v0;
            *(float2*)(out + (size_t)(m + 8) * H_ + g) = v1;
        }
    }
}

// ===========================================================================
// Phase 2: persistent scan (R12 exact: Wh in registers, 4-group sub-barriers)
// ===========================================================================
#define GT 64
#define KT 512
#define WST 520
#define HST 520
#define O_HH  0
#define O_HL  (B_ * HST)
#define O_RED (2 * B_ * HST)
#define SC_SMEM_BYTES (2 * GT * WST * 2)   // 133120

__global__ __launch_bounds__(256, 1)
void rnn_scan(float* __restrict__ out)
{
    extern __shared__ __align__(16) __nv_bfloat16 sm[];
    __nv_bfloat16* whh_s = sm;
    __nv_bfloat16* whl_s = sm + GT * WST;
    __nv_bfloat16* hh_s  = sm + O_HH;
    __nv_bfloat16* hl_s  = sm + O_HL;
    float* red = (float*)(sm + O_RED);

    const int tid = threadIdx.x, lane = tid & 31, wid = tid >> 5;
    const int gi = blockIdx.x & 31;
    const int ki = blockIdx.x >> 5;
    const int g0 = gi * GT;
    const int k0 = ki * KT;

    const int wn = wid >> 1;
    const int kg = wid & 1;

    for (int i = tid; i < GT * (KT / 8); i += 256) {
        int row = i >> 6;
        int c8  = (i & 63) * 8;
        *(uint4*)(whh_s + row * WST + c8) =
            *(const uint4*)(g_whh + (size_t)(g0 + row) * H_ + k0 + c8);
        *(uint4*)(whl_s + row * WST + c8) =
            *(const uint4*)(g_whl + (size_t)(g0 + row) * H_ + k0 + c8);
    }
    __syncthreads();

    uint32_t Bh[2][8][4], Bl[2][8][4];
#pragma unroll
    for (int nt = 0; nt < 2; nt++) {
        const int br = wn * 16 + nt * 8 + (lane & 7);
        const uint32_t baseH = smem_u32(whh_s + br * WST + kg * 256 + (lane >> 3) * 8);
        const uint32_t baseL = smem_u32(whl_s + br * WST + kg * 256 + (lane >> 3) * 8);
#pragma unroll
        for (int ch = 0; ch < 8; ch++) {
            ldsm4(Bh[nt][ch], baseH + ch * 64);
            ldsm4(Bl[nt][ch], baseL + ch * 64);
        }
    }
    __syncthreads();

    const int r0 = lane >> 2, c0 = (lane & 3) * 2;
    const uint32_t aHb = smem_u32(hh_s + (lane & 15) * HST + ((lane >> 4) << 3));
    const uint32_t aLb = smem_u32(hl_s + (lane & 15) * HST + ((lane >> 4) << 3));

    unsigned* mybar = &g_bar2[(gi >> 3) * T_];
    unsigned* wtbar = &g_bar2[ki * T_];

    for (int t = 1; t < T_; ++t) {
        if (t >= 2) {
            if (tid == 0) {
                unsigned v;
                do {
                    asm volatile("ld.acquire.gpu.global.u32 %0, [%1];"
                                 : "=r"(v) : "l"(wtbar + (t - 1)) : "memory");
                } while (v < 32u);
            }
            __syncthreads();
        }

#pragma unroll
        for (int r = 0; r < 8; r++) {
            int fi = tid + r * 256;
            int b  = fi >> 7;
            int c4 = fi & 127;
            float4 h4 = ld_cg4(out + (size_t)b * TH_ + (size_t)(t - 1) * H_ + k0 + c4 * 4);
            union { __nv_bfloat16 bb[4]; uint2 u; } th, tl;
            float f[4] = {h4.x, h4.y, h4.z, h4.w};
#pragma unroll
            for (int q = 0; q < 4; q++) {
                th.bb[q] = __float2bfloat16_rn(f[q]);
                tl.bb[q] = __float2bfloat16_rn(f[q] - __bfloat162float(th.bb[q]));
            }
            *(uint2*)(hh_s + b * HST + c4 * 4) = th.u;
            *(uint2*)(hl_s + b * HST + c4 * 4) = tl.u;
        }
        __syncthreads();

        float accA[2][4], accB[2][4];
#pragma unroll
        for (int i = 0; i < 2; i++)
#pragma unroll
            for (int q = 0; q < 4; q++) { accA[i][q] = 0.0f; accB[i][q] = 0.0f; }

#pragma unroll
        for (int ch = 0; ch < 8; ch++) {
            const uint32_t off = kg * 512 + ch * 64;
            uint32_t ah0[4], ah1[4], al0[4], al1[4];
            ldsm4(ah0, aHb + off);
            ldsm4(ah1, aHb + off + 32);
            ldsm4(al0, aLb + off);
            ldsm4(al1, aLb + off + 32);
#pragma unroll
            for (int nt = 0; nt < 2; nt++) {
                mma16816(accA[nt], ah0, Bh[nt][ch][0], Bh[nt][ch][1]);
                mma16816(accA[nt], ah1, Bh[nt][ch][2], Bh[nt][ch][3]);
                mma16816(accB[nt], ah0, Bl[nt][ch][0], Bl[nt][ch][1]);
                mma16816(accB[nt], ah1, Bl[nt][ch][2], Bl[nt][ch][3]);
                mma16816(accB[nt], al0, Bh[nt][ch][0], Bh[nt][ch][1]);
                mma16816(accB[nt], al1, Bh[nt][ch][2], Bh[nt][ch][3]);
            }
        }

        float* rw = red + (wn * 32 + lane) * 8;
        if (kg == 1) {
#pragma unroll
            for (int nt = 0; nt < 2; nt++) {
                float4 v = { accA[nt][0] + accB[nt][0], accA[nt][1] + accB[nt][1],
                             accA[nt][2] + accB[nt][2], accA[nt][3] + accB[nt][3] };
                *(float4*)(rw + nt * 4) = v;
            }
        }
        __syncthreads();

        if (kg == 0) {
#pragma unroll
            for (int nt = 0; nt < 2; nt++) {
                float4 v = *(const float4*)(rw + nt * 4);
                float s0 = accA[nt][0] + accB[nt][0] + v.x;
                float s1 = accA[nt][1] + accB[nt][1] + v.y;
                float s2 = accA[nt][2] + accB[nt][2] + v.z;
                float s3 = accA[nt][3] + accB[nt][3] + v.w;
                const int gcol = g0 + wn * 16 + nt * 8 + c0;
                red_add_v2(out + (size_t)r0 * TH_ + (size_t)t * H_ + gcol, s0, s1);
                red_add_v2(out + (size_t)(r0 + 8) * TH_ + (size_t)t * H_ + gcol, s2, s3);
            }
        }

        __syncthreads();
        if (t < T_ - 1 && tid == 0) {
            asm volatile("red.release.gpu.global.add.u32 [%0], 1;"
                         :: "l"(mybar + t) : "memory");
        }
    }
}

// ---------------- h_last copy ----------------------------------------------
__global__ void hlast_kernel(const float* __restrict__ out,
                             float* __restrict__ hlast)
{
    int i = blockIdx.x * blockDim.x + threadIdx.x;
    if (i < B_ * H_) {
        int b = i / H_;
        int g = i % H_;
        hlast[i] = out[(size_t)b * TH_ + (size_t)(T_ - 1) * H_ + g];
    }
}

// ---------------- launch ----------------------------------------------------
extern "C" void kernel_launch(void* const* d_in, const int* in_sizes, int n_in,
                              void* d_out, int out_size)
{
    const float* x  = (const float*)d_in[0];
    const float* W  = (const float*)d_in[1];
    const float* bi = (const float*)d_in[2];
    float* out = (float*)d_out;

    cudaFuncSetAttribute(gemm_u_mma,
                         cudaFuncAttributeMaxDynamicSharedMemorySize,
                         P1_SMEM_BYTES);
    cudaFuncSetAttribute(rnn_scan,
                         cudaFuncAttributeMaxDynamicSharedMemorySize,
                         SC_SMEM_BYTES);

    zero_bar_kernel<<<(4 * T_ + 255) / 256, 256>>>();
    split_xw_kernel<<<XB + WB, 256>>>(x, W);

    dim3 ggrid(H_ / 128, (B_ * T_) / 128);   // (16, 64)
    gemm_u_mma<<<ggrid, 256, P1_SMEM_BYTES>>>(bi, out);

    rnn_scan<<<NBLK, 256, SC_SMEM_BYTES>>>(out);

    if (out_size >= B_ * T_ * H_ + B_ * H_) {
        hlast_kernel<<<(B_ * H_ + 255) / 256, 256>>>(out, out + (size_t)B_ * T_ * H_);
    }
}